// round 16
// baseline (speedup 1.0000x reference)
#include <cuda_runtime.h>
#include <math.h>
#include <stdint.h>

#define NNODES 100000
#define CIN    256
#define NHEADS 4
#define BPH    37
#define BPHB   74
#define TILE   64
#define NT     ((NNODES + TILE - 1) / TILE)   // 1563
#define NPAD   (NT * TILE)                    // 100032
#define DHEAD  64
#define XS     292                            // xsA stride (==4 mod 32: A-frag clean; cols 256..263 = ones block)
#define KS     72                             // ks stride  (transposed-A clean)
#define QS     68                             // qn stride  (A-frag clean)
#define NTHR   256

// ---------------- helpers ----------------
__device__ __forceinline__ float rna(float f) {
    unsigned int u;
    asm("cvt.rna.tf32.f32 %0, %1;" : "=r"(u) : "f"(f));
    return __uint_as_float(u);
}
__device__ __forceinline__ unsigned int fu(float f) { return __float_as_uint(f); }
__device__ __forceinline__ void mma8(float c[4], uint4 a, uint2 b) {
    asm volatile("mma.sync.aligned.m16n8k8.row.col.f32.tf32.tf32.f32 "
        "{%0,%1,%2,%3}, {%4,%5,%6,%7}, {%8,%9}, {%0,%1,%2,%3};"
        : "+f"(c[0]), "+f"(c[1]), "+f"(c[2]), "+f"(c[3])
        : "r"(a.x), "r"(a.y), "r"(a.z), "r"(a.w), "r"(b.x), "r"(b.y));
}

// ---------------- device scratch ----------------
__device__ float g_qn[(size_t)NHEADS * NPAD * DHEAD];   // normalized q, fp32
__device__ float g_part_kvs[BPH][NHEADS * DHEAD * CIN];
__device__ float g_part_kss[BPH][NHEADS * DHEAD];
__device__ float g_part_cs [BPH][CIN];
__device__ float g_kvs   [NHEADS * DHEAD * CIN];
__device__ float g_kssum [NHEADS * DHEAD];
__device__ float g_colsum[CIN];

extern __shared__ float smf[];

// =====================================================================
// Phase A: fused k/q-proj + kv GEMM with ones-column (ks_sum in mma) + qn STG
// smem floats: xsA 18688 | wtk 16384 | wtq 16384 | ks 4608 | biask 64 |
//  biasq 64 | red 256 | redq 256 | inv 64 | qinv 64 | csred 1024
//  = 57856 (231424 B)
// =====================================================================
__global__ __launch_bounds__(NTHR, 1)
void phaseA_kernel(const float* __restrict__ x,
                   const float* __restrict__ Wk,
                   const float* __restrict__ bk,
                   const float* __restrict__ Wq,
                   const float* __restrict__ bq)
{
    const int h = blockIdx.y, bx = blockIdx.x, tid = threadIdx.x;
    const int lane = tid & 31, w = tid >> 5;
    const int gq = lane >> 2, ct = lane & 3;

    float* xsA   = smf;              // [64][292]
    float* wtk   = xsA + 18688;      // [256][64] swizzled: phys_m = m ^ (8*(c&3))
    float* wtq   = wtk + 16384;      // [256][64] swizzled
    float* ks    = wtq + 16384;      // [64][KS] raw (bias added, NOT normalized)
    float* biask = ks + 4608;
    float* biasq = biask + 64;
    float* red   = biasq + 64;       // [256]
    float* redq  = red + 256;        // [256]
    float* inv   = redq + 256;       // [64]
    float* qinv  = inv + 64;         // [64]
    float* csred = qinv + 64;        // [256][4]

    for (int i = tid; i < 16384; i += NTHR) {
        int c = i >> 6, m = i & 63;
        int sm = m ^ (8 * (c & 3));
        wtk[c * 64 + sm] = rna(Wk[(h * 64 + m) * 256 + c]);
        wtq[c * 64 + sm] = rna(Wq[(h * 64 + m) * 256 + c]);
    }
    if (tid < 64) { biask[tid] = bk[h * 64 + tid]; biasq[tid] = bq[h * 64 + tid]; }
    // ones-column block: cols 256..263 = {1,0,0,0,0,0,0,0} for every row (written once)
    for (int i = tid; i < 64 * 8; i += NTHR) {
        int n = i >> 3, c = 256 + (i & 7);
        xsA[n * XS + c] = (c == 256) ? 1.0f : 0.0f;
    }

    const int p2 = w & 1, nq = w >> 1;   // proj: 2 row-slabs(32) x 4 col-quarters(16)
    const int km = w >> 2, cq = w & 3;   // kv:   2 m-slabs(32) x 4 c-quarters(64) (+ ones tile for cq==3)

    float kvC[2][9][4];
    #pragma unroll
    for (int mi = 0; mi < 2; mi++)
        #pragma unroll
        for (int t = 0; t < 9; t++) {
            kvC[mi][t][0]=0.f; kvC[mi][t][1]=0.f; kvC[mi][t][2]=0.f; kvC[mi][t][3]=0.f;
        }
    float4 csacc = make_float4(0.f, 0.f, 0.f, 0.f);

    float4 pf[8];
    {
        const int base = bx * TILE;
        const int valid = (NNODES - base < TILE) ? (NNODES - base) : TILE;
        #pragma unroll
        for (int j = 0; j < 8; j++) {
            int i = tid + j * NTHR;
            int n = i >> 6, c4 = (i & 63) << 2;
            pf[j] = (n < valid) ? *(const float4*)(x + (size_t)(base + n) * CIN + c4)
                                : make_float4(0.f, 0.f, 0.f, 0.f);
        }
    }
    __syncthreads();

    for (int tile = bx; tile < NT; tile += BPH) {
        const int base = tile * TILE;
        const int valid = (NNODES - base < TILE) ? (NNODES - base) : TILE;

        // ---- store tile + colsum partials
        #pragma unroll
        for (int j = 0; j < 8; j++) {
            int i = tid + j * NTHR;
            int n = i >> 6, c4 = (i & 63) << 2;
            float4 v = pf[j];
            csacc.x += v.x; csacc.y += v.y; csacc.z += v.z; csacc.w += v.w;
            *(float4*)(xsA + n * XS + c4) =
                make_float4(rna(v.x), rna(v.y), rna(v.z), rna(v.w));
        }
        #pragma unroll
        for (int j = 8; j < 16; j++) {
            int i = tid + j * NTHR;
            int n = i >> 6, c4 = (i & 63) << 2;
            float4 v = (n < valid) ? *(const float4*)(x + (size_t)(base + n) * CIN + c4)
                                   : make_float4(0.f, 0.f, 0.f, 0.f);
            csacc.x += v.x; csacc.y += v.y; csacc.z += v.z; csacc.w += v.w;
            *(float4*)(xsA + n * XS + c4) =
                make_float4(rna(v.x), rna(v.y), rna(v.z), rna(v.w));
        }
        __syncthreads();

        if (tile + BPH < NT) {
            const int nb = (tile + BPH) * TILE;
            const int nv = (NNODES - nb < TILE) ? (NNODES - nb) : TILE;
            #pragma unroll
            for (int j = 0; j < 8; j++) {
                int i = tid + j * NTHR;
                int n = i >> 6, c4 = (i & 63) << 2;
                pf[j] = (n < nv) ? *(const float4*)(x + (size_t)(nb + n) * CIN + c4)
                                 : make_float4(0.f, 0.f, 0.f, 0.f);
            }
        }

        // ---- fused k/q-proj: 32 rows x 16 cols per warp (b-frags reused 2x)
        float qc[2][2][4];
        {
            float pck[2][2][4];
            #pragma unroll
            for (int mi = 0; mi < 2; mi++)
                #pragma unroll
                for (int t = 0; t < 2; t++) {
                    pck[mi][t][0]=0.f; pck[mi][t][1]=0.f; pck[mi][t][2]=0.f; pck[mi][t][3]=0.f;
                    qc [mi][t][0]=0.f; qc [mi][t][1]=0.f; qc [mi][t][2]=0.f; qc [mi][t][3]=0.f;
                }
            #pragma unroll 2
            for (int kb = 0; kb < 32; kb++) {
                const float* xr = xsA + (p2 * 32 + gq) * XS + kb * 8 + ct;
                uint4 a0, a1;
                a0.x = fu(xr[0]);       a0.y = fu(xr[8 * XS]);
                a0.z = fu(xr[4]);       a0.w = fu(xr[8 * XS + 4]);
                const float* xr2 = xr + 16 * XS;
                a1.x = fu(xr2[0]);      a1.y = fu(xr2[8 * XS]);
                a1.z = fu(xr2[4]);      a1.w = fu(xr2[8 * XS + 4]);
                #pragma unroll
                for (int t = 0; t < 2; t++) {
                    int off = (kb * 8 + ct) * 64 + ((nq * 16 + t * 8 + gq) ^ (8 * ct));
                    uint2 b;
                    b.x = fu(wtk[off]); b.y = fu(wtk[off + 4 * 64]);
                    mma8(pck[0][t], a0, b);
                    mma8(pck[1][t], a1, b);
                    uint2 b2;
                    b2.x = fu(wtq[off]); b2.y = fu(wtq[off + 4 * 64]);
                    mma8(qc[0][t], a0, b2);
                    mma8(qc[1][t], a1, b2);
                }
            }
            #pragma unroll
            for (int mi = 0; mi < 2; mi++) {
                int r0 = p2 * 32 + mi * 16 + gq;
                float nrm0 = 0.f, nrm1 = 0.f, qn0 = 0.f, qn1 = 0.f;
                #pragma unroll
                for (int t = 0; t < 2; t++) {
                    int cb = nq * 16 + t * 8 + 2 * ct;
                    float bk0 = biask[cb], bk1 = biask[cb + 1];
                    float bq0 = biasq[cb], bq1 = biasq[cb + 1];
                    float v0 = pck[mi][t][0] + bk0, v1 = pck[mi][t][1] + bk1;
                    float v2 = pck[mi][t][2] + bk0, v3 = pck[mi][t][3] + bk1;
                    *(float2*)(ks + r0 * KS + cb)       = make_float2(v0, v1);
                    *(float2*)(ks + (r0 + 8) * KS + cb) = make_float2(v2, v3);
                    nrm0 += v0 * v0 + v1 * v1;
                    nrm1 += v2 * v2 + v3 * v3;
                    qc[mi][t][0] += bq0; qc[mi][t][1] += bq1;
                    qc[mi][t][2] += bq0; qc[mi][t][3] += bq1;
                    qn0 += qc[mi][t][0] * qc[mi][t][0] + qc[mi][t][1] * qc[mi][t][1];
                    qn1 += qc[mi][t][2] * qc[mi][t][2] + qc[mi][t][3] * qc[mi][t][3];
                }
                nrm0 += __shfl_xor_sync(0xffffffffu, nrm0, 1);
                nrm0 += __shfl_xor_sync(0xffffffffu, nrm0, 2);
                nrm1 += __shfl_xor_sync(0xffffffffu, nrm1, 1);
                nrm1 += __shfl_xor_sync(0xffffffffu, nrm1, 2);
                qn0 += __shfl_xor_sync(0xffffffffu, qn0, 1);
                qn0 += __shfl_xor_sync(0xffffffffu, qn0, 2);
                qn1 += __shfl_xor_sync(0xffffffffu, qn1, 1);
                qn1 += __shfl_xor_sync(0xffffffffu, qn1, 2);
                if (ct == 0) {
                    red [r0 * 4 + nq] = nrm0;  red [(r0 + 8) * 4 + nq] = nrm1;
                    redq[r0 * 4 + nq] = qn0;   redq[(r0 + 8) * 4 + nq] = qn1;
                }
            }
        }
        __syncthreads();

        if (tid < 64) {
            float s = red[tid*4] + red[tid*4+1] + red[tid*4+2] + red[tid*4+3];
            inv[tid] = (tid < valid) ? rsqrtf(s) : 0.f;
        } else if (tid < 128) {
            int n = tid - 64;
            float s = redq[n*4] + redq[n*4+1] + redq[n*4+2] + redq[n*4+3];
            qinv[n] = (n < valid) ? rsqrtf(s) : 0.f;
        }
        __syncthreads();

        // ---- qn store to gmem (registers -> STG)
        {
            #pragma unroll
            for (int mi = 0; mi < 2; mi++) {
                int r0 = p2 * 32 + mi * 16 + gq;
                float iq0 = qinv[r0], iq1 = qinv[r0 + 8];
                float* q0 = g_qn + ((size_t)h * NPAD + base + r0) * DHEAD;
                float* q1 = g_qn + ((size_t)h * NPAD + base + r0 + 8) * DHEAD;
                #pragma unroll
                for (int t = 0; t < 2; t++) {
                    int cb = nq * 16 + t * 8 + 2 * ct;
                    *(float2*)(q0 + cb) = make_float2(qc[mi][t][0] * iq0, qc[mi][t][1] * iq0);
                    *(float2*)(q1 + cb) = make_float2(qc[mi][t][2] * iq1, qc[mi][t][3] * iq1);
                }
            }
        }

        // ---- kv += ks^T @ [x | 1 0..0]  (ks_sum emerges in column 256)
        {
            #pragma unroll
            for (int kb = 0; kb < 8; kb++) {
                int n0 = kb * 8 + ct;
                float iv0 = inv[n0], iv1 = inv[n0 + 4];
                uint4 a0, a1;
                {
                    const float* kp = ks + n0 * KS + km * 32 + gq;
                    a0.x = fu(rna(kp[0]  * iv0));          a0.y = fu(rna(kp[8]  * iv0));
                    a0.z = fu(rna(kp[4 * KS] * iv1));      a0.w = fu(rna(kp[4 * KS + 8] * iv1));
                    a1.x = fu(rna(kp[16] * iv0));          a1.y = fu(rna(kp[24] * iv0));
                    a1.z = fu(rna(kp[4 * KS + 16] * iv1)); a1.w = fu(rna(kp[4 * KS + 24] * iv1));
                }
                const float* xb0 = xsA + n0 * XS;
                const float* xb1 = xsA + (n0 + 4) * XS;
                #pragma unroll
                for (int t = 0; t < 8; t++) {
                    int c = cq * 64 + t * 8 + gq;
                    uint2 b; b.x = fu(xb0[c]); b.y = fu(xb1[c]);
                    mma8(kvC[0][t], a0, b);
                    mma8(kvC[1][t], a1, b);
                }
                if (cq == 3) {   // ones-column tile: c = 256..263
                    int c = 256 + gq;
                    uint2 b; b.x = fu(xb0[c]); b.y = fu(xb1[c]);
                    mma8(kvC[0][8], a0, b);
                    mma8(kvC[1][8], a1, b);
                }
            }
        }
        __syncthreads();
    }

    // ---- deterministic per-block partials
    {
        float* dst = g_part_kvs[bx] + h * (DHEAD * CIN);
        #pragma unroll
        for (int mi = 0; mi < 2; mi++)
            #pragma unroll
            for (int t = 0; t < 8; t++) {
                int c0 = cq * 64 + t * 8 + 2 * ct;
                int m0 = km * 32 + mi * 16 + gq;
                dst[m0 * 256 + c0]           = kvC[mi][t][0];
                dst[m0 * 256 + c0 + 1]       = kvC[mi][t][1];
                dst[(m0 + 8) * 256 + c0]     = kvC[mi][t][2];
                dst[(m0 + 8) * 256 + c0 + 1] = kvC[mi][t][3];
            }
    }
    // ks_sum from ones-column (col 256 -> ct==0 lanes of cq==3 warps)
    if (cq == 3 && ct == 0) {
        #pragma unroll
        for (int mi = 0; mi < 2; mi++) {
            int m0 = km * 32 + mi * 16 + gq;
            g_part_kss[bx][h * 64 + m0]     = kvC[mi][8][0];
            g_part_kss[bx][h * 64 + m0 + 8] = kvC[mi][8][2];
        }
    }
    {
        int c4 = (tid & 63) * 4, grp = tid >> 6;
        csred[(c4+0)*4+grp] = csacc.x; csred[(c4+1)*4+grp] = csacc.y;
        csred[(c4+2)*4+grp] = csacc.z; csred[(c4+3)*4+grp] = csacc.w;
    }
    __syncthreads();
    if (h == 0)
        g_part_cs[bx][tid] = csred[tid*4] + csred[tid*4+1] + csred[tid*4+2] + csred[tid*4+3];
}

// =====================================================================
// Reduce
// =====================================================================
__global__ void reduce_kernel()
{
    int i = blockIdx.x * 256 + threadIdx.x;
    if (i < NHEADS * DHEAD * CIN) {
        float s = 0.f;
        #pragma unroll 1
        for (int b = 0; b < BPH; b++) s += g_part_kvs[b][i];
        g_kvs[i] = s;
    }
    if (i < NHEADS * DHEAD) {
        float s = 0.f;
        for (int b = 0; b < BPH; b++) s += g_part_kss[b][i];
        g_kssum[i] = s;
    }
    if (i < CIN) {
        float s = 0.f;
        for (int b = 0; b < BPH; b++) s += g_part_cs[b][i];
        g_colsum[i] = s;
    }
}

// =====================================================================
// Phase B: pure out-GEMM from precomputed qn  (2 blocks/SM)
// smem floats: qsn 4352 | kvs 16384 | kss 64 | cs 256 | red2 256 | rno 64
//  = 21376 (85504 B)
// =====================================================================
__global__ __launch_bounds__(NTHR, 2)
void phaseB_kernel(float* __restrict__ out)
{
    const int h = blockIdx.y, tid = threadIdx.x;
    const int lane = tid & 31, w = tid >> 5;
    const int gq = lane >> 2, ct = lane & 3;

    float* qsn  = smf;             // [64][QS]
    float* kvs  = qsn + 4352;      // [64][256] swizzled: phys_c = c ^ (8*(m&3))
    float* kss  = kvs + 16384;
    float* cs   = kss + 64;
    float* red2 = cs + 256;        // [256]
    float* rno  = red2 + 256;      // [64]

    for (int i = tid; i < 16384; i += NTHR) {
        int m = i >> 8, c = i & 255;
        kvs[m * 256 + (c ^ (8 * (m & 3)))] = rna(g_kvs[h * 16384 + m * 256 + c]);
    }
    if (tid < 64) kss[tid] = g_kssum[h * 64 + tid];
    cs[tid] = g_colsum[tid];

    const int sn = w >> 2, cq = w & 3;

    float4 pf[4];
    {
        const int base = blockIdx.x * TILE;
        #pragma unroll
        for (int j = 0; j < 4; j++) {
            int s = tid + j * NTHR;
            int n = s >> 4, c4 = (s & 15) * 4;
            pf[j] = *(const float4*)(g_qn + ((size_t)h * NPAD + base + n) * DHEAD + c4);
        }
    }
    __syncthreads();

    for (int tile = blockIdx.x; tile < NT; tile += BPHB) {
        const int base = tile * TILE;
        const int valid = (NNODES - base < TILE) ? (NNODES - base) : TILE;

        #pragma unroll
        for (int j = 0; j < 4; j++) {
            int s = tid + j * NTHR;
            int n = s >> 4, c4 = (s & 15) * 4;
            *(float4*)(qsn + n * QS + c4) = pf[j];
        }
        __syncthreads();

        if (tile + BPHB < NT) {
            const int nb = (tile + BPHB) * TILE;
            #pragma unroll
            for (int j = 0; j < 4; j++) {
                int s = tid + j * NTHR;
                int n = s >> 4, c4 = (s & 15) * 4;
                pf[j] = *(const float4*)(g_qn + ((size_t)h * NPAD + nb + n) * DHEAD + c4);
            }
        }

        // ---- normalizer: dot(qn, ks_sum) per row
        {
            int n = tid >> 2, q = tid & 3;
            const float* qr = qsn + n * QS + q * 16;
            const float* kr = kss + q * 16;
            float d = 0.f;
            #pragma unroll
            for (int i2 = 0; i2 < 16; i2++) d += qr[i2] * kr[i2];
            red2[n * 4 + q] = d;
        }
        __syncthreads();
        if (tid < 64) {
            float d = red2[tid*4] + red2[tid*4+1] + red2[tid*4+2] + red2[tid*4+3];
            rno[tid] = 1.0f / (d + (float)NNODES);
        }
        __syncthreads();

        // ---- out = (qn @ kvs + colsum) * rno
        {
            float oc[2][8][4];
            #pragma unroll
            for (int mi = 0; mi < 2; mi++)
                #pragma unroll
                for (int t = 0; t < 8; t++) {
                    oc[mi][t][0]=0.f; oc[mi][t][1]=0.f; oc[mi][t][2]=0.f; oc[mi][t][3]=0.f;
                }
            int nbase = sn * 32 + gq;
            #pragma unroll
            for (int kb = 0; kb < 8; kb++) {
                uint4 a0, a1;
                {
                    const float* ap = qsn + nbase * QS + kb * 8 + ct;
                    a0.x = fu(rna(ap[0]));          a0.y = fu(rna(ap[8 * QS]));
                    a0.z = fu(rna(ap[4]));          a0.w = fu(rna(ap[8 * QS + 4]));
                    const float* ap1 = ap + 16 * QS;
                    a1.x = fu(rna(ap1[0]));         a1.y = fu(rna(ap1[8 * QS]));
                    a1.z = fu(rna(ap1[4]));         a1.w = fu(rna(ap1[8 * QS + 4]));
                }
                const float* kp0 = kvs + (kb * 8 + ct) * 256;
                const float* kp1 = kvs + (kb * 8 + ct + 4) * 256;
                const int sw = 8 * ct;
                #pragma unroll
                for (int t = 0; t < 8; t++) {
                    int c = cq * 64 + t * 8 + gq;
                    uint2 b; b.x = fu(kp0[c ^ sw]); b.y = fu(kp1[c ^ sw]);
                    mma8(oc[0][t], a0, b);
                    mma8(oc[1][t], a1, b);
                }
            }
            #pragma unroll
            for (int mi = 0; mi < 2; mi++) {
                int n0 = sn * 32 + mi * 16 + gq;
                float r0v = rno[n0], r1v = rno[n0 + 8];
                #pragma unroll
                for (int t = 0; t < 8; t++) {
                    int c0 = cq * 64 + t * 8 + 2 * ct;
                    float cv0 = cs[c0], cv1 = cs[c0 + 1];
                    if (n0 < valid)
                        *(float2*)(out + (size_t)(base + n0) * (NHEADS * CIN) + h * CIN + c0) =
                            make_float2((oc[mi][t][0] + cv0) * r0v, (oc[mi][t][1] + cv1) * r0v);
                    if (n0 + 8 < valid)
                        *(float2*)(out + (size_t)(base + n0 + 8) * (NHEADS * CIN) + h * CIN + c0) =
                            make_float2((oc[mi][t][2] + cv0) * r1v, (oc[mi][t][3] + cv1) * r1v);
                }
            }
        }
        __syncthreads();
    }
}

// =====================================================================
extern "C" void kernel_launch(void* const* d_in, const int* in_sizes, int n_in,
                              void* d_out, int out_size)
{
    const float* x    = (const float*)d_in[0];
    const float* Wq_w = (const float*)d_in[1];
    const float* Wq_b = (const float*)d_in[2];
    const float* Wk_w = (const float*)d_in[3];
    const float* Wk_b = (const float*)d_in[4];
    float* out = (float*)d_out;

    const int smemA = 57856 * (int)sizeof(float);   // 231424 B
    const int smemB = 21376 * (int)sizeof(float);   // 85504 B

    cudaFuncSetAttribute(phaseA_kernel, cudaFuncAttributeMaxDynamicSharedMemorySize, smemA);
    cudaFuncSetAttribute(phaseB_kernel, cudaFuncAttributeMaxDynamicSharedMemorySize, smemB);

    phaseA_kernel<<<dim3(BPH, NHEADS), NTHR, smemA>>>(x, Wk_w, Wk_b, Wq_w, Wq_b);
    reduce_kernel<<<256, 256>>>();
    phaseB_kernel<<<dim3(BPHB, NHEADS), NTHR, smemB>>>(out);
}

// round 17
// speedup vs baseline: 1.0241x; 1.0241x over previous
#include <cuda_runtime.h>
#include <math.h>
#include <stdint.h>

#define NNODES 100000
#define CIN    256
#define NHEADS 4
#define BPH    37
#define BPHB   74
#define TILE   64
#define NT     ((NNODES + TILE - 1) / TILE)   // 1563
#define NPAD   (NT * TILE)                    // 100032
#define DHEAD  64
#define XS     292                            // xsA stride (==4 mod 32; cols 256..263 = ones block)
#define KS     72                             // ks stride  (transposed-A clean)
#define QS     68                             // qn stride  (==4 mod 32: A-frag/LDSM clean)
#define NTHR   256

// ---------------- helpers ----------------
__device__ __forceinline__ float rna(float f) {
    unsigned int u;
    asm("cvt.rna.tf32.f32 %0, %1;" : "=r"(u) : "f"(f));
    return __uint_as_float(u);
}
__device__ __forceinline__ unsigned int fu(float f) { return __float_as_uint(f); }
__device__ __forceinline__ void mma8(float c[4], uint4 a, uint2 b) {
    asm volatile("mma.sync.aligned.m16n8k8.row.col.f32.tf32.tf32.f32 "
        "{%0,%1,%2,%3}, {%4,%5,%6,%7}, {%8,%9}, {%0,%1,%2,%3};"
        : "+f"(c[0]), "+f"(c[1]), "+f"(c[2]), "+f"(c[3])
        : "r"(a.x), "r"(a.y), "r"(a.z), "r"(a.w), "r"(b.x), "r"(b.y));
}
// tf32 m16k8 A-fragment via one ldmatrix.x4 (16x16 b16 view); lane gives its row ptr
__device__ __forceinline__ void ldsm4(uint4 &a, const float* p) {
    unsigned int addr = (unsigned int)__cvta_generic_to_shared(p);
    asm volatile("ldmatrix.sync.aligned.m8n8.x4.shared.b16 {%0,%1,%2,%3}, [%4];"
        : "=r"(a.x), "=r"(a.y), "=r"(a.z), "=r"(a.w) : "r"(addr));
}

// ---------------- device scratch ----------------
__device__ float g_qn[(size_t)NHEADS * NPAD * DHEAD];   // normalized q (tf32-rounded)
__device__ float g_part_kvs[BPH][NHEADS * DHEAD * CIN];
__device__ float g_part_kss[BPH][NHEADS * DHEAD];
__device__ float g_part_cs [BPH][CIN];
__device__ float g_kvs   [NHEADS * DHEAD * CIN];
__device__ float g_kssum [NHEADS * DHEAD];
__device__ float g_colsum[CIN];

extern __shared__ float smf[];

// =====================================================================
// Phase A: fused k/q-proj (LDSM A-frags) + kv GEMM w/ ones-column + qn STG
// smem floats: xsA 18688 | wtk 16384 | wtq 16384 | ks 4608 | biask 64 |
//  biasq 64 | red 256 | redq 256 | inv 64 | qinv 64 | csred 1024
//  = 57856 (231424 B)
// =====================================================================
__global__ __launch_bounds__(NTHR, 1)
void phaseA_kernel(const float* __restrict__ x,
                   const float* __restrict__ Wk,
                   const float* __restrict__ bk,
                   const float* __restrict__ Wq,
                   const float* __restrict__ bq)
{
    const int h = blockIdx.y, bx = blockIdx.x, tid = threadIdx.x;
    const int lane = tid & 31, w = tid >> 5;
    const int gq = lane >> 2, ct = lane & 3;

    float* xsA   = smf;              // [64][292]
    float* wtk   = xsA + 18688;      // [256][64] swizzled: phys_m = m ^ (8*(c&3))
    float* wtq   = wtk + 16384;      // [256][64] swizzled
    float* ks    = wtq + 16384;      // [64][KS] raw (bias added, NOT normalized)
    float* biask = ks + 4608;
    float* biasq = biask + 64;
    float* red   = biasq + 64;       // [256]
    float* redq  = red + 256;        // [256]
    float* inv   = redq + 256;       // [64]
    float* qinv  = inv + 64;         // [64]
    float* csred = qinv + 64;        // [256][4]

    for (int i = tid; i < 16384; i += NTHR) {
        int c = i >> 6, m = i & 63;
        int sm = m ^ (8 * (c & 3));
        wtk[c * 64 + sm] = rna(Wk[(h * 64 + m) * 256 + c]);
        wtq[c * 64 + sm] = rna(Wq[(h * 64 + m) * 256 + c]);
    }
    if (tid < 64) { biask[tid] = bk[h * 64 + tid]; biasq[tid] = bq[h * 64 + tid]; }
    // ones-column block: cols 256..263 = {1,0,...}
    for (int i = tid; i < 64 * 8; i += NTHR) {
        int n = i >> 3, c = 256 + (i & 7);
        xsA[n * XS + c] = (c == 256) ? 1.0f : 0.0f;
    }

    const int p2 = w & 1, nq = w >> 1;   // proj: 2 row-slabs(32) x 4 col-quarters(16)
    const int km = w >> 2, cq = w & 3;   // kv:   2 m-slabs(32) x 4 c-quarters(64)

    // ldmatrix lane base offsets for proj A-frags
    const int li = lane & 7, seg = lane >> 3;
    const int aoff0 = (p2 * 32 + (seg & 1) * 8 + li) * XS + (seg >> 1) * 4;
    const int aoff1 = aoff0 + 16 * XS;

    float kvC[2][9][4];
    #pragma unroll
    for (int mi = 0; mi < 2; mi++)
        #pragma unroll
        for (int t = 0; t < 9; t++) {
            kvC[mi][t][0]=0.f; kvC[mi][t][1]=0.f; kvC[mi][t][2]=0.f; kvC[mi][t][3]=0.f;
        }
    float4 csacc = make_float4(0.f, 0.f, 0.f, 0.f);

    float4 pf[8];
    {
        const int base = bx * TILE;
        const int valid = (NNODES - base < TILE) ? (NNODES - base) : TILE;
        #pragma unroll
        for (int j = 0; j < 8; j++) {
            int i = tid + j * NTHR;
            int n = i >> 6, c4 = (i & 63) << 2;
            pf[j] = (n < valid) ? *(const float4*)(x + (size_t)(base + n) * CIN + c4)
                                : make_float4(0.f, 0.f, 0.f, 0.f);
        }
    }
    __syncthreads();

    for (int tile = bx; tile < NT; tile += BPH) {
        const int base = tile * TILE;
        const int valid = (NNODES - base < TILE) ? (NNODES - base) : TILE;

        // ---- store tile + colsum partials
        #pragma unroll
        for (int j = 0; j < 8; j++) {
            int i = tid + j * NTHR;
            int n = i >> 6, c4 = (i & 63) << 2;
            float4 v = pf[j];
            csacc.x += v.x; csacc.y += v.y; csacc.z += v.z; csacc.w += v.w;
            *(float4*)(xsA + n * XS + c4) =
                make_float4(rna(v.x), rna(v.y), rna(v.z), rna(v.w));
        }
        #pragma unroll
        for (int j = 8; j < 16; j++) {
            int i = tid + j * NTHR;
            int n = i >> 6, c4 = (i & 63) << 2;
            float4 v = (n < valid) ? *(const float4*)(x + (size_t)(base + n) * CIN + c4)
                                   : make_float4(0.f, 0.f, 0.f, 0.f);
            csacc.x += v.x; csacc.y += v.y; csacc.z += v.z; csacc.w += v.w;
            *(float4*)(xsA + n * XS + c4) =
                make_float4(rna(v.x), rna(v.y), rna(v.z), rna(v.w));
        }
        __syncthreads();

        if (tile + BPH < NT) {
            const int nb = (tile + BPH) * TILE;
            const int nv = (NNODES - nb < TILE) ? (NNODES - nb) : TILE;
            #pragma unroll
            for (int j = 0; j < 8; j++) {
                int i = tid + j * NTHR;
                int n = i >> 6, c4 = (i & 63) << 2;
                pf[j] = (n < nv) ? *(const float4*)(x + (size_t)(nb + n) * CIN + c4)
                                 : make_float4(0.f, 0.f, 0.f, 0.f);
            }
        }

        // ---- fused k/q-proj: LDSM A-frags, b-frags reused 2x
        float qc[2][2][4];
        {
            float pck[2][2][4];
            #pragma unroll
            for (int mi = 0; mi < 2; mi++)
                #pragma unroll
                for (int t = 0; t < 2; t++) {
                    pck[mi][t][0]=0.f; pck[mi][t][1]=0.f; pck[mi][t][2]=0.f; pck[mi][t][3]=0.f;
                    qc [mi][t][0]=0.f; qc [mi][t][1]=0.f; qc [mi][t][2]=0.f; qc [mi][t][3]=0.f;
                }
            #pragma unroll 2
            for (int kb = 0; kb < 32; kb++) {
                uint4 a0, a1;
                ldsm4(a0, xsA + aoff0 + kb * 8);
                ldsm4(a1, xsA + aoff1 + kb * 8);
                #pragma unroll
                for (int t = 0; t < 2; t++) {
                    int off = (kb * 8 + ct) * 64 + ((nq * 16 + t * 8 + gq) ^ (8 * ct));
                    uint2 b;
                    b.x = fu(wtk[off]); b.y = fu(wtk[off + 4 * 64]);
                    mma8(pck[0][t], a0, b);
                    mma8(pck[1][t], a1, b);
                    uint2 b2;
                    b2.x = fu(wtq[off]); b2.y = fu(wtq[off + 4 * 64]);
                    mma8(qc[0][t], a0, b2);
                    mma8(qc[1][t], a1, b2);
                }
            }
            #pragma unroll
            for (int mi = 0; mi < 2; mi++) {
                int r0 = p2 * 32 + mi * 16 + gq;
                float nrm0 = 0.f, nrm1 = 0.f, qn0 = 0.f, qn1 = 0.f;
                #pragma unroll
                for (int t = 0; t < 2; t++) {
                    int cb = nq * 16 + t * 8 + 2 * ct;
                    float bk0 = biask[cb], bk1 = biask[cb + 1];
                    float bq0 = biasq[cb], bq1 = biasq[cb + 1];
                    float v0 = pck[mi][t][0] + bk0, v1 = pck[mi][t][1] + bk1;
                    float v2 = pck[mi][t][2] + bk0, v3 = pck[mi][t][3] + bk1;
                    *(float2*)(ks + r0 * KS + cb)       = make_float2(v0, v1);
                    *(float2*)(ks + (r0 + 8) * KS + cb) = make_float2(v2, v3);
                    nrm0 += v0 * v0 + v1 * v1;
                    nrm1 += v2 * v2 + v3 * v3;
                    qc[mi][t][0] += bq0; qc[mi][t][1] += bq1;
                    qc[mi][t][2] += bq0; qc[mi][t][3] += bq1;
                    qn0 += qc[mi][t][0] * qc[mi][t][0] + qc[mi][t][1] * qc[mi][t][1];
                    qn1 += qc[mi][t][2] * qc[mi][t][2] + qc[mi][t][3] * qc[mi][t][3];
                }
                nrm0 += __shfl_xor_sync(0xffffffffu, nrm0, 1);
                nrm0 += __shfl_xor_sync(0xffffffffu, nrm0, 2);
                nrm1 += __shfl_xor_sync(0xffffffffu, nrm1, 1);
                nrm1 += __shfl_xor_sync(0xffffffffu, nrm1, 2);
                qn0 += __shfl_xor_sync(0xffffffffu, qn0, 1);
                qn0 += __shfl_xor_sync(0xffffffffu, qn0, 2);
                qn1 += __shfl_xor_sync(0xffffffffu, qn1, 1);
                qn1 += __shfl_xor_sync(0xffffffffu, qn1, 2);
                if (ct == 0) {
                    red [r0 * 4 + nq] = nrm0;  red [(r0 + 8) * 4 + nq] = nrm1;
                    redq[r0 * 4 + nq] = qn0;   redq[(r0 + 8) * 4 + nq] = qn1;
                }
            }
        }
        __syncthreads();

        if (tid < 64) {
            float s = red[tid*4] + red[tid*4+1] + red[tid*4+2] + red[tid*4+3];
            inv[tid] = (tid < valid) ? rsqrtf(s) : 0.f;
        } else if (tid < 128) {
            int n = tid - 64;
            float s = redq[n*4] + redq[n*4+1] + redq[n*4+2] + redq[n*4+3];
            qinv[n] = (n < valid) ? rsqrtf(s) : 0.f;
        }
        __syncthreads();

        // ---- qn store to gmem (tf32-rounded; phaseB loads raw via LDSM)
        {
            #pragma unroll
            for (int mi = 0; mi < 2; mi++) {
                int r0 = p2 * 32 + mi * 16 + gq;
                float iq0 = qinv[r0], iq1 = qinv[r0 + 8];
                float* q0 = g_qn + ((size_t)h * NPAD + base + r0) * DHEAD;
                float* q1 = g_qn + ((size_t)h * NPAD + base + r0 + 8) * DHEAD;
                #pragma unroll
                for (int t = 0; t < 2; t++) {
                    int cb = nq * 16 + t * 8 + 2 * ct;
                    *(float2*)(q0 + cb) = make_float2(rna(qc[mi][t][0] * iq0), rna(qc[mi][t][1] * iq0));
                    *(float2*)(q1 + cb) = make_float2(rna(qc[mi][t][2] * iq1), rna(qc[mi][t][3] * iq1));
                }
            }
        }

        // ---- kv += ks^T @ [x | 1 0..0]  (ks_sum emerges in column 256)
        {
            #pragma unroll
            for (int kb = 0; kb < 8; kb++) {
                int n0 = kb * 8 + ct;
                float iv0 = inv[n0], iv1 = inv[n0 + 4];
                uint4 a0, a1;
                {
                    const float* kp = ks + n0 * KS + km * 32 + gq;
                    a0.x = fu(rna(kp[0]  * iv0));          a0.y = fu(rna(kp[8]  * iv0));
                    a0.z = fu(rna(kp[4 * KS] * iv1));      a0.w = fu(rna(kp[4 * KS + 8] * iv1));
                    a1.x = fu(rna(kp[16] * iv0));          a1.y = fu(rna(kp[24] * iv0));
                    a1.z = fu(rna(kp[4 * KS + 16] * iv1)); a1.w = fu(rna(kp[4 * KS + 24] * iv1));
                }
                const float* xb0 = xsA + n0 * XS;
                const float* xb1 = xsA + (n0 + 4) * XS;
                #pragma unroll
                for (int t = 0; t < 8; t++) {
                    int c = cq * 64 + t * 8 + gq;
                    uint2 b; b.x = fu(xb0[c]); b.y = fu(xb1[c]);
                    mma8(kvC[0][t], a0, b);
                    mma8(kvC[1][t], a1, b);
                }
                if (cq == 3) {
                    int c = 256 + gq;
                    uint2 b; b.x = fu(xb0[c]); b.y = fu(xb1[c]);
                    mma8(kvC[0][8], a0, b);
                    mma8(kvC[1][8], a1, b);
                }
            }
        }
        __syncthreads();
    }

    // ---- deterministic per-block partials
    {
        float* dst = g_part_kvs[bx] + h * (DHEAD * CIN);
        #pragma unroll
        for (int mi = 0; mi < 2; mi++)
            #pragma unroll
            for (int t = 0; t < 8; t++) {
                int c0 = cq * 64 + t * 8 + 2 * ct;
                int m0 = km * 32 + mi * 16 + gq;
                dst[m0 * 256 + c0]           = kvC[mi][t][0];
                dst[m0 * 256 + c0 + 1]       = kvC[mi][t][1];
                dst[(m0 + 8) * 256 + c0]     = kvC[mi][t][2];
                dst[(m0 + 8) * 256 + c0 + 1] = kvC[mi][t][3];
            }
    }
    if (cq == 3 && ct == 0) {
        #pragma unroll
        for (int mi = 0; mi < 2; mi++) {
            int m0 = km * 32 + mi * 16 + gq;
            g_part_kss[bx][h * 64 + m0]     = kvC[mi][8][0];
            g_part_kss[bx][h * 64 + m0 + 8] = kvC[mi][8][2];
        }
    }
    {
        int c4 = (tid & 63) * 4, grp = tid >> 6;
        csred[(c4+0)*4+grp] = csacc.x; csred[(c4+1)*4+grp] = csacc.y;
        csred[(c4+2)*4+grp] = csacc.z; csred[(c4+3)*4+grp] = csacc.w;
    }
    __syncthreads();
    if (h == 0)
        g_part_cs[bx][tid] = csred[tid*4] + csred[tid*4+1] + csred[tid*4+2] + csred[tid*4+3];
}

// =====================================================================
// Reduce
// =====================================================================
__global__ void reduce_kernel()
{
    int i = blockIdx.x * 256 + threadIdx.x;
    if (i < NHEADS * DHEAD * CIN) {
        float s = 0.f;
        #pragma unroll 1
        for (int b = 0; b < BPH; b++) s += g_part_kvs[b][i];
        g_kvs[i] = s;
    }
    if (i < NHEADS * DHEAD) {
        float s = 0.f;
        for (int b = 0; b < BPH; b++) s += g_part_kss[b][i];
        g_kssum[i] = s;
    }
    if (i < CIN) {
        float s = 0.f;
        for (int b = 0; b < BPH; b++) s += g_part_cs[b][i];
        g_colsum[i] = s;
    }
}

// =====================================================================
// Phase B: pure out-GEMM from precomputed qn (LDSM A-frags, 2 blocks/SM)
// smem floats: qsn 4352 | kvs 16384 | kss 64 | cs 256 | red2 256 | rno 64
//  = 21376 (85504 B)
// =====================================================================
__global__ __launch_bounds__(NTHR, 2)
void phaseB_kernel(float* __restrict__ out)
{
    const int h = blockIdx.y, tid = threadIdx.x;
    const int lane = tid & 31, w = tid >> 5;
    const int gq = lane >> 2, ct = lane & 3;

    float* qsn  = smf;             // [64][QS] (tf32-rounded values)
    float* kvs  = qsn + 4352;      // [64][256] swizzled: phys_c = c ^ (8*(m&3))
    float* kss  = kvs + 16384;
    float* cs   = kss + 64;
    float* red2 = cs + 256;        // [256]
    float* rno  = red2 + 256;      // [64]

    for (int i = tid; i < 16384; i += NTHR) {
        int m = i >> 8, c = i & 255;
        kvs[m * 256 + (c ^ (8 * (m & 3)))] = rna(g_kvs[h * 16384 + m * 256 + c]);
    }
    if (tid < 64) kss[tid] = g_kssum[h * 64 + tid];
    cs[tid] = g_colsum[tid];

    const int sn = w >> 2, cq = w & 3;

    const int li = lane & 7, seg = lane >> 3;
    const int boff0 = (sn * 32 + (seg & 1) * 8 + li) * QS + (seg >> 1) * 4;
    const int boff1 = boff0 + 16 * QS;

    float4 pf[4];
    {
        const int base = blockIdx.x * TILE;
        #pragma unroll
        for (int j = 0; j < 4; j++) {
            int s = tid + j * NTHR;
            int n = s >> 4, c4 = (s & 15) * 4;
            pf[j] = *(const float4*)(g_qn + ((size_t)h * NPAD + base + n) * DHEAD + c4);
        }
    }
    __syncthreads();

    for (int tile = blockIdx.x; tile < NT; tile += BPHB) {
        const int base = tile * TILE;
        const int valid = (NNODES - base < TILE) ? (NNODES - base) : TILE;

        #pragma unroll
        for (int j = 0; j < 4; j++) {
            int s = tid + j * NTHR;
            int n = s >> 4, c4 = (s & 15) * 4;
            *(float4*)(qsn + n * QS + c4) = pf[j];
        }
        __syncthreads();

        if (tile + BPHB < NT) {
            const int nb = (tile + BPHB) * TILE;
            #pragma unroll
            for (int j = 0; j < 4; j++) {
                int s = tid + j * NTHR;
                int n = s >> 4, c4 = (s & 15) * 4;
                pf[j] = *(const float4*)(g_qn + ((size_t)h * NPAD + nb + n) * DHEAD + c4);
            }
        }

        // ---- normalizer: dot(qn, ks_sum) per row
        {
            int n = tid >> 2, q = tid & 3;
            const float* qr = qsn + n * QS + q * 16;
            const float* kr = kss + q * 16;
            float d = 0.f;
            #pragma unroll
            for (int i2 = 0; i2 < 16; i2++) d += qr[i2] * kr[i2];
            red2[n * 4 + q] = d;
        }
        __syncthreads();
        if (tid < 64) {
            float d = red2[tid*4] + red2[tid*4+1] + red2[tid*4+2] + red2[tid*4+3];
            rno[tid] = 1.0f / (d + (float)NNODES);
        }
        __syncthreads();

        // ---- out = (qn @ kvs + colsum) * rno  (LDSM A-frags)
        {
            float oc[2][8][4];
            #pragma unroll
            for (int mi = 0; mi < 2; mi++)
                #pragma unroll
                for (int t = 0; t < 8; t++) {
                    oc[mi][t][0]=0.f; oc[mi][t][1]=0.f; oc[mi][t][2]=0.f; oc[mi][t][3]=0.f;
                }
            #pragma unroll
            for (int kb = 0; kb < 8; kb++) {
                uint4 a0, a1;
                ldsm4(a0, qsn + boff0 + kb * 8);
                ldsm4(a1, qsn + boff1 + kb * 8);
                const float* kp0 = kvs + (kb * 8 + ct) * 256;
                const float* kp1 = kvs + (kb * 8 + ct + 4) * 256;
                const int sw = 8 * ct;
                #pragma unroll
                for (int t = 0; t < 8; t++) {
                    int c = cq * 64 + t * 8 + gq;
                    uint2 b; b.x = fu(kp0[c ^ sw]); b.y = fu(kp1[c ^ sw]);
                    mma8(oc[0][t], a0, b);
                    mma8(oc[1][t], a1, b);
                }
            }
            #pragma unroll
            for (int mi = 0; mi < 2; mi++) {
                int n0 = sn * 32 + mi * 16 + gq;
                float r0v = rno[n0], r1v = rno[n0 + 8];
                #pragma unroll
                for (int t = 0; t < 8; t++) {
                    int c0 = cq * 64 + t * 8 + 2 * ct;
                    float cv0 = cs[c0], cv1 = cs[c0 + 1];
                    if (n0 < valid)
                        *(float2*)(out + (size_t)(base + n0) * (NHEADS * CIN) + h * CIN + c0) =
                            make_float2((oc[mi][t][0] + cv0) * r0v, (oc[mi][t][1] + cv1) * r0v);
                    if (n0 + 8 < valid)
                        *(float2*)(out + (size_t)(base + n0 + 8) * (NHEADS * CIN) + h * CIN + c0) =
                            make_float2((oc[mi][t][2] + cv0) * r1v, (oc[mi][t][3] + cv1) * r1v);
                }
            }
        }
        __syncthreads();
    }
}

// =====================================================================
extern "C" void kernel_launch(void* const* d_in, const int* in_sizes, int n_in,
                              void* d_out, int out_size)
{
    const float* x    = (const float*)d_in[0];
    const float* Wq_w = (const float*)d_in[1];
    const float* Wq_b = (const float*)d_in[2];
    const float* Wk_w = (const float*)d_in[3];
    const float* Wk_b = (const float*)d_in[4];
    float* out = (float*)d_out;

    const int smemA = 57856 * (int)sizeof(float);   // 231424 B
    const int smemB = 21376 * (int)sizeof(float);   // 85504 B

    cudaFuncSetAttribute(phaseA_kernel, cudaFuncAttributeMaxDynamicSharedMemorySize, smemA);
    cudaFuncSetAttribute(phaseB_kernel, cudaFuncAttributeMaxDynamicSharedMemorySize, smemB);

    phaseA_kernel<<<dim3(BPH, NHEADS), NTHR, smemA>>>(x, Wk_w, Wk_b, Wq_w, Wq_b);
    reduce_kernel<<<256, 256>>>();
    phaseB_kernel<<<dim3(BPHB, NHEADS), NTHR, smemB>>>(out);
}